// round 2
// baseline (speedup 1.0000x reference)
#include <cuda_runtime.h>

#define BB 8
#define CC 48
#define HH 128
#define HW 16384
#define WR 65
#define NHEADS 4

// freq layout: [b][path(re/im)][c][wr][h]  -- contiguous in h
#define FOFF(b,p,c,wr) ((((((size_t)(b))*2+(p))*CC+(c))*WR+(wr))*HH)

// ---------------- scratch ----------------------------------------------------
__device__ float g_ap[BB*CC];
__device__ float g_filt[BB*8*9];
__device__ float g_low [BB*CC*HW];
__device__ float g_hf  [BB*CC*HW];
__device__ float g_lf  [BB*CC*HW];
__device__ float g_freq[BB*2*CC*WR*HH];
__device__ float g_bufA[BB*CC*HW];
__device__ float g_q   [BB*CC*HW];
__device__ float g_bufC[BB*2*CC*HW];
__device__ float g_bufD[BB*2*CC*HW];
__device__ float g_kvh [BB*2*CC*HW];
__device__ float g_kvl [BB*2*CC*HW];
__device__ float g_G   [2*BB*NHEADS*168];
__device__ float g_N   [2*BB*CC*CC];

__device__ __forceinline__ float gelu_exact(float v){
    return 0.5f*v*(1.0f + erff(v*0.70710678118654752440f));
}

// ---------------- K0: zero accumulators -------------------------------------
__global__ void k_zero(){
    int i = blockIdx.x*256 + threadIdx.x;
    if (i < BB*CC) g_ap[i] = 0.f;
    if (i < 2*BB*NHEADS*168) g_G[i] = 0.f;
}

// ---------------- K1: per-(b,c) spatial mean (tiled + atomic) ----------------
__global__ void k_mean(const float* __restrict__ x){
    int bc = blockIdx.x;
    const float* p = x + (size_t)bc*HW + blockIdx.y*4096;
    float s = 0.f;
    for (int i = threadIdx.x; i < 4096; i += 256) s += p[i];
    int lane = threadIdx.x & 31;
    for (int o = 16; o; o >>= 1) s += __shfl_down_sync(0xffffffffu, s, o);
    __shared__ float sm[8];
    if (lane == 0) sm[threadIdx.x>>5] = s;
    __syncthreads();
    if (threadIdx.x == 0){
        float t = 0.f;
        #pragma unroll
        for (int i = 0; i < 8; i++) t += sm[i];
        atomicAdd(&g_ap[bc], t * (1.0f/HW));
    }
}

// ---------------- K2: dynamic filter (1x1 + BN + group softmax) --------------
__global__ void k_filt(const float* __restrict__ fdw, const float* __restrict__ gg,
                       const float* __restrict__ bb, const float* __restrict__ mm,
                       const float* __restrict__ vv){
    __shared__ float lf[72];
    int b = blockIdx.x, o = threadIdx.x;
    if (o < 72){
        float a = 0.f;
        #pragma unroll
        for (int c = 0; c < CC; c++) a += g_ap[b*CC+c]*fdw[o*CC+c];
        a = (a - mm[o]) * rsqrtf(vv[o] + 1e-5f) * gg[o] + bb[o];
        lf[o] = a;
    }
    __syncthreads();
    if (o < 8){
        float mx = -1e30f;
        for (int k = 0; k < 9; k++) mx = fmaxf(mx, lf[o*9+k]);
        float e[9], s = 0.f;
        for (int k = 0; k < 9; k++){ e[k] = expf(lf[o*9+k]-mx); s += e[k]; }
        for (int k = 0; k < 9; k++) g_filt[(b*8+o)*9+k] = e[k]/s;
    }
}

// ---------------- K3: fused low/high split + high-gate (haloed row tile) ----
__global__ void __launch_bounds__(256)
k_split(const float* __restrict__ x, const float* __restrict__ w1,
        const float* __restrict__ b1, const float* __restrict__ w2,
        const float* __restrict__ b2){
    int bc = blockIdx.x; int b = bc/CC, c = bc%CC, g = c/6;
    int r0 = blockIdx.y*16;
    __shared__ float xs[20][128];
    __shared__ float hs[18][128];
    __shared__ float f[9], a1[3], a2[3], bias1, bias2;
    int t = threadIdx.x;
    if (t < 9) f[t] = g_filt[(b*8+g)*9+t];
    if (t < 3){ a1[t] = w1[c*3+t]; a2[t] = w2[c*3+t]; }
    if (t == 0){ bias1 = b1[c]; bias2 = b2[c]; }
    const float* xp = x + (size_t)bc*HW;
    for (int idx = t; idx < 20*128; idx += 256){
        int rr = idx >> 7, w = idx & 127;
        int h = r0 - 2 + rr; h = h < 0 ? -h : (h > 127 ? 254-h : h);
        xs[rr][w] = xp[h*128 + w];
    }
    __syncthreads();
    float* lo = g_low + (size_t)bc*HW;
    for (int idx = t; idx < 18*128; idx += 256){
        int k = idx >> 7, w = idx & 127;
        int h = r0 - 1 + k;
        float acc = 0.f;
        #pragma unroll
        for (int i = 0; i < 3; i++){
            #pragma unroll
            for (int j = 0; j < 3; j++){
                int ww = w + j - 1; ww = ww < 0 ? -ww : (ww > 127 ? 254-ww : ww);
                acc += f[i*3+j]*xs[k+i][ww];
            }
        }
        float hv = 0.f;
        if (h >= 0 && h <= 127){
            hv = xs[k+1][w] - acc;
            if (k >= 1 && k <= 16) lo[h*128 + w] = acc;
        }
        hs[k][w] = hv;
    }
    __syncthreads();
    float* hf = g_hf + (size_t)bc*HW;
    for (int idx = t; idx < 16*128; idx += 256){
        int k = idx >> 7, w = idx & 127;
        int h = r0 + k;
        float acc = bias2;
        #pragma unroll
        for (int i = 0; i < 3; i++){
            int hr = h + i - 1; if (hr < 0 || hr > 127) continue;
            float tt = bias1;
            #pragma unroll
            for (int j = 0; j < 3; j++){
                int ww = w + j - 1; if (ww < 0 || ww > 127) continue;
                tt += a1[j]*hs[k+i][ww];
            }
            acc += a2[i]*tt;
        }
        hf[h*128 + w] = gelu_exact(acc) * hs[k+1][w];
    }
}

// ---------------- warp-cooperative 128-pt radix-2 FFT ------------------------
__device__ __forceinline__ void fft128(float2* s, int lane, float sgn){
    #pragma unroll
    for (int r = 0; r < 4; r++){
        int i = lane + r*32;
        int j = (int)(__brev((unsigned)i) >> 25);
        if (i < j){ float2 t = s[i]; s[i] = s[j]; s[j] = t; }
    }
    __syncwarp();
    #pragma unroll
    for (int st = 1; st <= 7; st++){
        int len = 1 << st, half = len >> 1;
        float invh = 1.0f/(float)half;
        #pragma unroll
        for (int r = 0; r < 2; r++){
            int t = lane + r*32;
            int grp = t >> (st-1);
            int pos = t & (half-1);
            int i = grp*len + pos;
            float sp, cp;
            sincospif((float)pos*invh, &sp, &cp);
            float wx = cp, wy = sgn*sp;
            float2 u = s[i]; float2 q = s[i+half];
            float vx = q.x*wx - q.y*wy;
            float vy = q.x*wy + q.y*wx;
            s[i]       = make_float2(u.x+vx, u.y+vy);
            s[i+half]  = make_float2(u.x-vx, u.y-vy);
        }
        __syncwarp();
    }
}

// ---------------- K5: row rFFT (writes transposed, coalesced) ---------------
__global__ void __launch_bounds__(256)
k_rowfft(){
    __shared__ float2 sm[32][129];
    int bc = blockIdx.x; int b = bc/CC, c = bc%CC;
    int h0 = blockIdx.y*32;
    int w8 = threadIdx.x >> 5, lane = threadIdx.x & 31;
    const float* base = g_low + (size_t)bc*HW;
    #pragma unroll
    for (int rr = 0; rr < 4; rr++){
        int hh = w8*4 + rr;
        const float* row = base + (h0 + hh)*128;
        float2* s = sm[hh];
        #pragma unroll
        for (int q = 0; q < 4; q++){ int i = lane + 32*q; s[i] = make_float2(row[i], 0.f); }
        __syncwarp();
        fft128(s, lane, -1.f);
    }
    __syncthreads();
    float* re = g_freq + FOFF(b,0,c,0);
    float* im = g_freq + FOFF(b,1,c,0);
    for (int idx = threadIdx.x; idx < WR*32; idx += 256){
        int wr = idx >> 5, hh = idx & 31;
        float2 v = sm[hh][wr];
        re[(size_t)wr*HH + h0 + hh] = v.x;
        im[(size_t)wr*HH + h0 + hh] = v.y;
    }
}

// ---------------- K6: column FFT (contiguous in h now) -----------------------
__global__ void __launch_bounds__(256)
k_colfft(float sgn){
    __shared__ float2 sm[8][130];
    int w8 = threadIdx.x >> 5, lane = threadIdx.x & 31;
    int j = blockIdx.x*8 + w8;            // (b,c,wr) job, 24960 total
    int b = j/(CC*WR); int r = j%(CC*WR); int c = r/WR; int wr = r%WR;
    float* re = g_freq + FOFF(b,0,c,wr);
    float* im = g_freq + FOFF(b,1,c,wr);
    float2* s = sm[w8];
    #pragma unroll
    for (int rr = 0; rr < 4; rr++){ int h = lane + 32*rr; s[h] = make_float2(re[h], im[h]); }
    __syncwarp();
    fft128(s, lane, sgn);
    #pragma unroll
    for (int rr = 0; rr < 4; rr++){ int h = lane + 32*rr; re[h] = s[h].x; im[h] = s[h].y; }
}

// ---------------- K7: frequency-domain gated channel mix ---------------------
__global__ void __launch_bounds__(256)
k_mix(const float* __restrict__ flw, const float* __restrict__ flb){
    __shared__ float yf[96*64];
    int id = blockIdx.x;
    int b = id/(WR*2); int rem = id%(WR*2); int wr = rem >> 1; int h0 = (rem & 1)*64;
    int t = threadIdx.x;
    for (int idx = t; idx < 96*64; idx += 256){
        int cc = idx >> 6, hh = idx & 63;
        yf[idx] = g_freq[FOFF(b, cc/48, cc%48, wr) + h0 + hh];
    }
    __syncthreads();
    for (int task = t; task < 96*64; task += 256){
        int o = task >> 6, hh = task & 63;
        float acc = __ldg(&flb[o]);
        const float* wrow = flw + o*96;
        #pragma unroll
        for (int c2 = 0; c2 < 96; c2++) acc += __ldg(&wrow[c2])*yf[c2*64 + hh];
        float ov = yf[task] * gelu_exact(acc);
        g_freq[FOFF(b, o/48, o%48, wr) + h0 + hh] = ov;
    }
}

// ---------------- K8: inverse row FFT (hermitian rebuild) --------------------
__global__ void __launch_bounds__(256)
k_rowifft(){
    __shared__ float2 sm[32][129];
    int bc = blockIdx.x; int b = bc/CC, c = bc%CC;
    int h0 = blockIdx.y*32;
    const float* re = g_freq + FOFF(b,0,c,0);
    const float* im = g_freq + FOFF(b,1,c,0);
    for (int idx = threadIdx.x; idx < WR*32; idx += 256){
        int wr = idx >> 5, hh = idx & 31;
        sm[hh][wr] = make_float2(re[(size_t)wr*HH + h0 + hh], im[(size_t)wr*HH + h0 + hh]);
    }
    __syncthreads();
    int w8 = threadIdx.x >> 5, lane = threadIdx.x & 31;
    float* outb = g_lf + (size_t)bc*HW;
    #pragma unroll
    for (int rr = 0; rr < 4; rr++){
        int hh = w8*4 + rr;
        float2* s = sm[hh];
        for (int k = WR + lane; k < 128; k += 32){ float2 m = s[128-k]; s[k] = make_float2(m.x, -m.y); }
        __syncwarp();
        fft128(s, lane, 1.f);
        #pragma unroll
        for (int q = 0; q < 4; q++){ int i = lane + 32*q; outb[(h0+hh)*128 + i] = s[i].x * (1.0f/16384.0f); }
    }
}

// ---------------- 1x1 conv (48 -> COUT), weights via __ldg broadcast --------
template<int COUT>
__global__ void __launch_bounds__(256)
k_conv1x1(const float* __restrict__ in, const float* __restrict__ w,
          float* __restrict__ out){
    __shared__ float si[CC*128];
    int b = blockIdx.y; int p0 = blockIdx.x*128; int t = threadIdx.x;
    for (int idx = t; idx < CC*128; idx += 256){
        int c = idx >> 7, p = idx & 127;
        si[idx] = in[(size_t)(b*CC + c)*HW + p0 + p];
    }
    __syncthreads();
    for (int task = t; task < COUT*128; task += 256){
        int o = task >> 7, p = task & 127;
        float acc = 0.f;
        #pragma unroll
        for (int c = 0; c < CC; c++) acc += __ldg(&w[o*CC + c])*si[c*128 + p];
        out[(size_t)(b*COUT + o)*HW + p0 + p] = acc;
    }
}

// ---------------- both-path kv 1x1 conv (reads x once) -----------------------
__global__ void __launch_bounds__(256)
k_convkv(const float* __restrict__ x, const float* __restrict__ wh,
         const float* __restrict__ wl){
    __shared__ float si[CC*128];
    int b = blockIdx.y; int p0 = blockIdx.x*128; int t = threadIdx.x;
    for (int idx = t; idx < CC*128; idx += 256){
        int c = idx >> 7, p = idx & 127;
        si[idx] = x[(size_t)(b*CC + c)*HW + p0 + p];
    }
    __syncthreads();
    for (int task = t; task < 192*128; task += 256){
        int o = task >> 7, p = task & 127;
        const float* wp = (o < 96) ? (wh + o*CC) : (wl + (o-96)*CC);
        float acc = 0.f;
        #pragma unroll
        for (int c = 0; c < CC; c++) acc += __ldg(&wp[c])*si[c*128 + p];
        float* outp = (o < 96) ? (g_bufC + (size_t)(b*96 + o)*HW)
                               : (g_bufD + (size_t)(b*96 + o - 96)*HW);
        outp[p0 + p] = acc;
    }
}

// ---------------- depthwise 3x3, zero pad, tiled -----------------------------
__global__ void __launch_bounds__(256)
k_dw3(const float* __restrict__ in, const float* __restrict__ w9,
      float* __restrict__ out, int Ctot){
    int bc = blockIdx.x; int c = bc % Ctot; int r0 = blockIdx.y*32;
    __shared__ float f[9];
    if (threadIdx.x < 9) f[threadIdx.x] = w9[c*9 + threadIdx.x];
    __syncthreads();
    const float* p = in + (size_t)bc*HW;
    float* o = out + (size_t)bc*HW;
    for (int px = threadIdx.x; px < 4096; px += 256){
        int h = r0 + (px >> 7), w = px & 127;
        float acc = 0.f;
        #pragma unroll
        for (int i = 0; i < 3; i++){
            int hh = h + i - 1; if (hh < 0 || hh > 127) continue;
            #pragma unroll
            for (int j = 0; j < 3; j++){
                int ww = w + j - 1; if (ww < 0 || ww > 127) continue;
                acc += f[i*3+j]*p[hh*128+ww];
            }
        }
        o[h*128 + w] = acc;
    }
}

// ---------------- fused gram + squared norms ---------------------------------
__global__ void __launch_bounds__(256,1)
k_gram(const float* __restrict__ q, const float* __restrict__ kv, float* __restrict__ G){
    int bh = blockIdx.x; int b = bh/NHEADS, hd = bh%NHEADS;
    const float* qb = q  + (size_t)(b*CC    + hd*12)*HW + blockIdx.y*1024;
    const float* kb = kv + (size_t)(b*2*CC + hd*12)*HW + blockIdx.y*1024;
    float acc[168];
    #pragma unroll
    for (int i = 0; i < 168; i++) acc[i] = 0.f;
    for (int p = threadIdx.x; p < 1024; p += 256){
        float qv[12], kvv[12];
        #pragma unroll
        for (int d = 0; d < 12; d++){ qv[d] = qb[d*HW + p]; kvv[d] = kb[d*HW + p]; }
        #pragma unroll
        for (int d = 0; d < 12; d++){
            #pragma unroll
            for (int e = 0; e < 12; e++) acc[d*12+e] += qv[d]*kvv[e];
            acc[144+d] += qv[d]*qv[d];
            acc[156+d] += kvv[d]*kvv[d];
        }
    }
    int lane = threadIdx.x & 31;
    float* Gp = G + bh*168;
    #pragma unroll
    for (int i = 0; i < 168; i++){
        float v = acc[i];
        for (int off = 16; off; off >>= 1) v += __shfl_down_sync(0xffffffffu, v, off);
        if (lane == 0) atomicAdd(&Gp[i], v);
    }
}

// ---------------- per-batch fused N = fp_slice @ pw @ BD(softmax(S)) ---------
__global__ void k_prepN(const float* __restrict__ pw, const float* __restrict__ temp,
                        const float* __restrict__ fpw, int path){
    int b = blockIdx.x, t = threadIdx.x;
    __shared__ float A[4*12*12];
    __shared__ float M[48*48];
    const float* Gb = g_G + ((size_t)path*BB + b)*NHEADS*168;
    if (t < 48){
        int hd = t/12, d = t%12;
        const float* Gh = Gb + hd*168;
        float nq = fmaxf(sqrtf(Gh[144+d]), 1e-12f);
        float tp = temp[hd];
        float row[12]; float mx = -1e30f;
        #pragma unroll
        for (int e = 0; e < 12; e++){
            float nk = fmaxf(sqrtf(Gh[156+e]), 1e-12f);
            row[e] = Gh[d*12+e]/(nq*nk)*tp;
            mx = fmaxf(mx, row[e]);
        }
        float s = 0.f;
        #pragma unroll
        for (int e = 0; e < 12; e++){ row[e] = expf(row[e]-mx); s += row[e]; }
        #pragma unroll
        for (int e = 0; e < 12; e++) A[(hd*12+d)*12 + e] = row[e]/s;
    }
    __syncthreads();
    for (int task = t; task < 2304; task += blockDim.x){
        int o = task/48, cg = task%48; int he = cg/12, e = cg%12;
        float acc = 0.f;
        #pragma unroll
        for (int d = 0; d < 12; d++) acc += pw[o*48 + he*12 + d]*A[(he*12+d)*12 + e];
        M[task] = acc;
    }
    __syncthreads();
    float* Nout = g_N + ((size_t)path*BB + b)*2304;
    for (int task = t; task < 2304; task += blockDim.x){
        int o2 = task/48, cg = task%48;
        float acc = 0.f;
        #pragma unroll
        for (int o = 0; o < 48; o++) acc += fpw[o2*96 + path*48 + o]*M[o*48 + cg];
        Nout[task] = acc;
    }
}

// ---------------- final fused: out = Nh@v_h + Nl@v_l + fp_b + x --------------
__global__ void __launch_bounds__(256)
k_final(const float* __restrict__ x, const float* __restrict__ fpb,
        float* __restrict__ out){
    __shared__ float sv[2*CC*64];
    __shared__ float sn[2*2304];
    int b = blockIdx.y; int p0 = blockIdx.x*64; int t = threadIdx.x;
    for (int idx = t; idx < 2304; idx += 256){
        sn[idx]        = g_N[(size_t)b*2304 + idx];
        sn[2304 + idx] = g_N[(size_t)(BB + b)*2304 + idx];
    }
    for (int idx = t; idx < CC*64; idx += 256){
        int c = idx >> 6, p = idx & 63;
        sv[idx]          = g_kvh[(size_t)(b*2*CC + CC + c)*HW + p0 + p];
        sv[CC*64 + idx]  = g_kvl[(size_t)(b*2*CC + CC + c)*HW + p0 + p];
    }
    __syncthreads();
    for (int task = t; task < CC*64; task += 256){
        int o = task >> 6, p = task & 63;
        float acc = __ldg(&fpb[o]);
        #pragma unroll
        for (int c = 0; c < CC; c++) acc += sn[o*CC + c]*sv[c*64 + p];
        #pragma unroll
        for (int c = 0; c < CC; c++) acc += sn[2304 + o*CC + c]*sv[CC*64 + c*64 + p];
        size_t gi = (size_t)(b*CC + o)*HW + p0 + p;
        out[gi] = acc + x[gi];
    }
}

// ============================================================================
extern "C" void kernel_launch(void* const* d_in, const int* in_sizes, int n_in,
                              void* d_out, int out_size){
    const float* x       = (const float*)d_in[0];
    const float* fd_w    = (const float*)d_in[1];
    const float* bn_g    = (const float*)d_in[2];
    const float* bn_b    = (const float*)d_in[3];
    const float* bn_m    = (const float*)d_in[4];
    const float* bn_v    = (const float*)d_in[5];
    const float* fh_w1   = (const float*)d_in[6];
    const float* fh_b1   = (const float*)d_in[7];
    const float* fh_w2   = (const float*)d_in[8];
    const float* fh_b2   = (const float*)d_in[9];
    const float* fl_w    = (const float*)d_in[10];
    const float* fl_b    = (const float*)d_in[11];
    const float* hfa_qw  = (const float*)d_in[12];
    const float* hfa_kvw = (const float*)d_in[13];
    const float* hfa_qdw = (const float*)d_in[14];
    const float* hfa_kvdw= (const float*)d_in[15];
    const float* hfa_pw  = (const float*)d_in[16];
    const float* hfa_t   = (const float*)d_in[17];
    const float* lfa_qw  = (const float*)d_in[18];
    const float* lfa_kvw = (const float*)d_in[19];
    const float* lfa_qdw = (const float*)d_in[20];
    const float* lfa_kvdw= (const float*)d_in[21];
    const float* lfa_pw  = (const float*)d_in[22];
    const float* lfa_t   = (const float*)d_in[23];
    const float* fp_w    = (const float*)d_in[24];
    const float* fp_b    = (const float*)d_in[25];

    float *p_hf, *p_lf, *p_bufA, *p_q, *p_bufC, *p_bufD, *p_kvh, *p_kvl, *p_G;
    cudaGetSymbolAddress((void**)&p_hf,   g_hf);
    cudaGetSymbolAddress((void**)&p_lf,   g_lf);
    cudaGetSymbolAddress((void**)&p_bufA, g_bufA);
    cudaGetSymbolAddress((void**)&p_q,    g_q);
    cudaGetSymbolAddress((void**)&p_bufC, g_bufC);
    cudaGetSymbolAddress((void**)&p_bufD, g_bufD);
    cudaGetSymbolAddress((void**)&p_kvh,  g_kvh);
    cudaGetSymbolAddress((void**)&p_kvl,  g_kvl);
    cudaGetSymbolAddress((void**)&p_G,    g_G);

    k_zero <<<44, 256>>>();
    k_mean <<<dim3(BB*CC, 4), 256>>>(x);
    k_filt <<<BB, 128>>>(fd_w, bn_g, bn_b, bn_m, bn_v);
    k_split<<<dim3(BB*CC, 8), 256>>>(x, fh_w1, fh_b1, fh_w2, fh_b2);

    // low branch: rfft2 -> gated channel mix -> irfft2 (transposed freq layout)
    k_rowfft <<<dim3(BB*CC, 4), 256>>>();
    k_colfft <<<3120, 256>>>(-1.f);
    k_mix    <<<BB*WR*2, 256>>>(fl_w, fl_b);
    k_colfft <<<3120, 256>>>(1.f);
    k_rowifft<<<dim3(BB*CC, 4), 256>>>();

    // kv for both paths (reads x once)
    k_convkv<<<dim3(128, BB), 256>>>(x, hfa_kvw, lfa_kvw);
    k_dw3   <<<dim3(BB*96, 4), 256>>>(p_bufC, hfa_kvdw, p_kvh, 96);
    k_dw3   <<<dim3(BB*96, 4), 256>>>(p_bufD, lfa_kvdw, p_kvl, 96);

    // fga high
    k_conv1x1<48><<<dim3(128, BB), 256>>>(p_hf, hfa_qw, p_bufA);
    k_dw3 <<<dim3(BB*CC, 4), 256>>>(p_bufA, hfa_qdw, p_q, CC);
    k_gram<<<dim3(BB*NHEADS, 16), 256>>>(p_q, p_kvh, p_G);
    k_prepN<<<BB, 256>>>(hfa_pw, hfa_t, fp_w, 0);

    // fga low
    k_conv1x1<48><<<dim3(128, BB), 256>>>(p_lf, lfa_qw, p_bufA);
    k_dw3 <<<dim3(BB*CC, 4), 256>>>(p_bufA, lfa_qdw, p_q, CC);
    k_gram<<<dim3(BB*NHEADS, 16), 256>>>(p_q, p_kvl, p_G + BB*NHEADS*168);
    k_prepN<<<BB, 256>>>(lfa_pw, lfa_t, fp_w, 1);

    // fused attn@v + pw + concat + fp + bias + residual
    k_final<<<dim3(256, BB), 256>>>(x, fp_b, (float*)d_out);
}

// round 3
// speedup vs baseline: 1.2721x; 1.2721x over previous
#include <cuda_runtime.h>

#define BB 8
#define CC 48
#define HH 128
#define HW 16384
#define WR 65
#define NHEADS 4

// freq layout: [b][re/im][c][wr][h]  -- contiguous in h
#define FOFF(b,p,c,wr) ((((((size_t)(b))*2+(p))*CC+(c))*WR+(wr))*HH)

// ---------------- scratch ----------------------------------------------------
__device__ float g_ap[BB*CC];
__device__ float g_filt[BB*8*9];
__device__ float g_low [BB*CC*HW];
__device__ float g_hf  [BB*CC*HW];
__device__ float g_lf  [BB*CC*HW];
__device__ float g_freq[BB*2*CC*WR*HH];
__device__ float g_kvh [BB*2*CC*HW];
__device__ float g_kvl [BB*2*CC*HW];
__device__ float g_G   [2*BB*NHEADS*168];
__device__ float g_N   [2*BB*CC*CC];

__constant__ float c_flw[96*96];
__constant__ float c_flb[96];

__device__ __forceinline__ float gelu_exact(float v){
    return 0.5f*v*(1.0f + erff(v*0.70710678118654752440f));
}

// ---------------- K1: per-(b,c) spatial mean ---------------------------------
__global__ void k_mean(const float* __restrict__ x){
    int bc = blockIdx.x;
    const float* p = x + (size_t)bc*HW;
    float s = 0.f;
    for (int i = threadIdx.x; i < HW; i += 256) s += p[i];
    int lane = threadIdx.x & 31;
    for (int o = 16; o; o >>= 1) s += __shfl_down_sync(0xffffffffu, s, o);
    __shared__ float sm[8];
    if (lane == 0) sm[threadIdx.x>>5] = s;
    __syncthreads();
    if (threadIdx.x == 0){
        float t = 0.f;
        #pragma unroll
        for (int i = 0; i < 8; i++) t += sm[i];
        g_ap[bc] = t * (1.0f/HW);
    }
}

// ---------------- K2: dynamic filter + zero gram accumulators ----------------
__global__ void k_filt(const float* __restrict__ fdw, const float* __restrict__ gg,
                       const float* __restrict__ bb, const float* __restrict__ mm,
                       const float* __restrict__ vv){
    __shared__ float lf[72];
    int b = blockIdx.x, o = threadIdx.x;
    for (int i = blockIdx.x*128 + threadIdx.x; i < 2*BB*NHEADS*168; i += BB*128)
        g_G[i] = 0.f;
    if (o < 72){
        float a = 0.f;
        #pragma unroll
        for (int c = 0; c < CC; c++) a += g_ap[b*CC+c]*fdw[o*CC+c];
        a = (a - mm[o]) * rsqrtf(vv[o] + 1e-5f) * gg[o] + bb[o];
        lf[o] = a;
    }
    __syncthreads();
    if (o < 8){
        float mx = -1e30f;
        for (int k = 0; k < 9; k++) mx = fmaxf(mx, lf[o*9+k]);
        float e[9], s = 0.f;
        for (int k = 0; k < 9; k++){ e[k] = expf(lf[o*9+k]-mx); s += e[k]; }
        for (int k = 0; k < 9; k++) g_filt[(b*8+o)*9+k] = e[k]/s;
    }
}

// ---------------- K3: fused low/high split + high-gate, padded shared --------
__global__ void __launch_bounds__(256)
k_split(const float* __restrict__ x, const float* __restrict__ w1,
        const float* __restrict__ b1, const float* __restrict__ w2,
        const float* __restrict__ b2){
    int bc = blockIdx.x; int b = bc/CC, c = bc%CC, g = c/6;
    int r0 = blockIdx.y*16;
    __shared__ float xs[20][130];
    __shared__ float hs[18][130];
    __shared__ float f[9], a1[3], a2[3], bias1, bias2;
    int t = threadIdx.x;
    if (t < 9) f[t] = g_filt[(b*8+g)*9+t];
    if (t < 3){ a1[t] = w1[c*3+t]; a2[t] = w2[c*3+t]; }
    if (t == 0){ bias1 = b1[c]; bias2 = b2[c]; }
    const float* xp = x + (size_t)bc*HW;
    for (int idx = t; idx < 20*130; idx += 256){
        int rr = idx/130, cc = idx%130;
        int h = r0 - 2 + rr; h = h < 0 ? -h : (h > 127 ? 254-h : h);
        int w = cc - 1;      w = w < 0 ? -w : (w > 127 ? 254-w : w);
        xs[rr][cc] = xp[h*128 + w];
    }
    __syncthreads();
    float* lo = g_low + (size_t)bc*HW;
    for (int idx = t; idx < 18*128; idx += 256){
        int k = idx >> 7, w = idx & 127;
        int h = r0 - 1 + k;
        float acc = f[0]*xs[k  ][w] + f[1]*xs[k  ][w+1] + f[2]*xs[k  ][w+2]
                  + f[3]*xs[k+1][w] + f[4]*xs[k+1][w+1] + f[5]*xs[k+1][w+2]
                  + f[6]*xs[k+2][w] + f[7]*xs[k+2][w+1] + f[8]*xs[k+2][w+2];
        float hv = 0.f;
        if (h >= 0 && h <= 127){
            hv = xs[k+1][w+1] - acc;
            if (k >= 1 && k <= 16) lo[h*128 + w] = acc;
        }
        hs[k][w+1] = hv;
    }
    if (t < 18){ hs[t][0] = 0.f; hs[t][129] = 0.f; }
    __syncthreads();
    float* hf = g_hf + (size_t)bc*HW;
    for (int idx = t; idx < 16*128; idx += 256){
        int k = idx >> 7, w = idx & 127;
        int h = r0 + k;
        float acc = bias2;
        #pragma unroll
        for (int i = 0; i < 3; i++){
            int hr = h + i - 1; if (hr < 0 || hr > 127) continue;
            float tt = bias1 + a1[0]*hs[k+i][w] + a1[1]*hs[k+i][w+1] + a1[2]*hs[k+i][w+2];
            acc += a2[i]*tt;
        }
        hf[h*128 + w] = gelu_exact(acc) * hs[k+1][w+1];
    }
}

// ---------------- warp FFTs --------------------------------------------------
__device__ __forceinline__ void fft128(float2* s, int lane, float sgn){
    #pragma unroll
    for (int r = 0; r < 4; r++){
        int i = lane + r*32;
        int j = (int)(__brev((unsigned)i) >> 25);
        if (i < j){ float2 t = s[i]; s[i] = s[j]; s[j] = t; }
    }
    __syncwarp();
    #pragma unroll
    for (int st = 1; st <= 7; st++){
        int half = 1 << (st-1);
        float invh = 1.0f/(float)half;
        #pragma unroll
        for (int r = 0; r < 2; r++){
            int t = lane + r*32;
            int grp = t >> (st-1), pos = t & (half-1);
            int i = grp*(half<<1) + pos;
            float sp, cp; sincospif((float)pos*invh, &sp, &cp);
            float wx = cp, wy = sgn*sp;
            float2 u = s[i]; float2 q = s[i+half];
            float vx = q.x*wx - q.y*wy, vy = q.x*wy + q.y*wx;
            s[i]      = make_float2(u.x+vx, u.y+vy);
            s[i+half] = make_float2(u.x-vx, u.y-vy);
        }
        __syncwarp();
    }
}

__device__ __forceinline__ void fft128_sp(float* re, float* im, int lane, float sgn){
    #pragma unroll
    for (int r = 0; r < 4; r++){
        int i = lane + r*32;
        int j = (int)(__brev((unsigned)i) >> 25);
        if (i < j){
            float tr = re[i]; re[i] = re[j]; re[j] = tr;
            float ti = im[i]; im[i] = im[j]; im[j] = ti;
        }
    }
    __syncwarp();
    #pragma unroll
    for (int st = 1; st <= 7; st++){
        int half = 1 << (st-1);
        float invh = 1.0f/(float)half;
        #pragma unroll
        for (int r = 0; r < 2; r++){
            int t = lane + r*32;
            int grp = t >> (st-1), pos = t & (half-1);
            int i = grp*(half<<1) + pos;
            float sp, cp; sincospif((float)pos*invh, &sp, &cp);
            float wx = cp, wy = sgn*sp;
            float ur = re[i], ui = im[i], qr = re[i+half], qi = im[i+half];
            float vr = qr*wx - qi*wy, vi = qr*wy + qi*wx;
            re[i] = ur+vr; im[i] = ui+vi;
            re[i+half] = ur-vr; im[i+half] = ui-vi;
        }
        __syncwarp();
    }
}

// ---------------- K5: row rFFT (writes transposed, coalesced) ----------------
__global__ void __launch_bounds__(256)
k_rowfft(){
    __shared__ float2 sm[32][129];
    int bc = blockIdx.x; int b = bc/CC, c = bc%CC;
    int h0 = blockIdx.y*32;
    int w8 = threadIdx.x >> 5, lane = threadIdx.x & 31;
    const float* base = g_low + (size_t)bc*HW;
    #pragma unroll
    for (int rr = 0; rr < 4; rr++){
        int hh = w8*4 + rr;
        const float* row = base + (h0 + hh)*128;
        float2* s = sm[hh];
        #pragma unroll
        for (int q = 0; q < 4; q++){ int i = lane + 32*q; s[i] = make_float2(row[i], 0.f); }
        __syncwarp();
        fft128(s, lane, -1.f);
    }
    __syncthreads();
    float* re = g_freq + FOFF(b,0,c,0);
    float* im = g_freq + FOFF(b,1,c,0);
    for (int idx = threadIdx.x; idx < WR*32; idx += 256){
        int wr = idx >> 5, hh = idx & 31;
        float2 v = sm[hh][wr];
        re[(size_t)wr*HH + h0 + hh] = v.x;
        im[(size_t)wr*HH + h0 + hh] = v.y;
    }
}

// ---------------- K6: fused column FFT -> gated channel mix -> column IFFT ---
__global__ void __launch_bounds__(256)
k_fftmix(){
    __shared__ float sre[48][128];
    __shared__ float sim[48][128];
    int b = blockIdx.x / WR, wr = blockIdx.x % WR;
    int t = threadIdx.x;
    for (int idx = t; idx < 48*128; idx += 256){
        int c = idx >> 7, h = idx & 127;
        sre[c][h] = g_freq[FOFF(b,0,c,wr) + h];
        sim[c][h] = g_freq[FOFF(b,1,c,wr) + h];
    }
    __syncthreads();
    int wp = t >> 5, lane = t & 31;
    for (int c = wp; c < 48; c += 8) fft128_sp(sre[c], sim[c], lane, -1.f);
    __syncthreads();
    float rout[48];
    #pragma unroll
    for (int k = 0; k < 48; k++){
        int task = t + k*256;
        int o = task >> 7, h = task & 127;
        float acc = c_flb[o];
        const float* wrow = c_flw + o*96;
        #pragma unroll
        for (int c2 = 0; c2 < 48; c2++) acc += wrow[c2]*sre[c2][h];
        #pragma unroll
        for (int c2 = 0; c2 < 48; c2++) acc += wrow[48+c2]*sim[c2][h];
        float yv = (o < 48) ? sre[o][h] : sim[o-48][h];
        rout[k] = yv * gelu_exact(acc);
    }
    __syncthreads();
    #pragma unroll
    for (int k = 0; k < 48; k++){
        int task = t + k*256;
        int o = task >> 7, h = task & 127;
        if (o < 48) sre[o][h] = rout[k]; else sim[o-48][h] = rout[k];
    }
    __syncthreads();
    for (int c = wp; c < 48; c += 8) fft128_sp(sre[c], sim[c], lane, 1.f);
    __syncthreads();
    for (int idx = t; idx < 48*128; idx += 256){
        int c = idx >> 7, h = idx & 127;
        g_freq[FOFF(b,0,c,wr) + h] = sre[c][h];
        g_freq[FOFF(b,1,c,wr) + h] = sim[c][h];
    }
}

// ---------------- K7: inverse row FFT (hermitian rebuild) --------------------
__global__ void __launch_bounds__(256)
k_rowifft(){
    __shared__ float2 sm[32][129];
    int bc = blockIdx.x; int b = bc/CC, c = bc%CC;
    int h0 = blockIdx.y*32;
    const float* re = g_freq + FOFF(b,0,c,0);
    const float* im = g_freq + FOFF(b,1,c,0);
    for (int idx = threadIdx.x; idx < WR*32; idx += 256){
        int wr = idx >> 5, hh = idx & 31;
        sm[hh][wr] = make_float2(re[(size_t)wr*HH + h0 + hh], im[(size_t)wr*HH + h0 + hh]);
    }
    __syncthreads();
    int w8 = threadIdx.x >> 5, lane = threadIdx.x & 31;
    float* outb = g_lf + (size_t)bc*HW;
    #pragma unroll
    for (int rr = 0; rr < 4; rr++){
        int hh = w8*4 + rr;
        float2* s = sm[hh];
        for (int k = WR + lane; k < 128; k += 32){ float2 m = s[128-k]; s[k] = make_float2(m.x, -m.y); }
        __syncwarp();
        fft128(s, lane, 1.f);
        #pragma unroll
        for (int q = 0; q < 4; q++){ int i = lane + 32*q; outb[(h0+hh)*128 + i] = s[i].x * (1.0f/16384.0f); }
    }
}

// ---------------- K8: fused kv conv1x1 + depthwise 3x3 (both paths) ----------
__global__ void __launch_bounds__(256)
k_convdw(const float* __restrict__ x, const float* __restrict__ wh,
         const float* __restrict__ wl, const float* __restrict__ dwh,
         const float* __restrict__ dwl){
    extern __shared__ float sh[];
    float* cs = sh;                 // 12*10*130
    float* sw = sh + 12*10*130;     // 12*48
    int g = blockIdx.x, rt = blockIdx.y, b = blockIdx.z;
    int og0 = g*12;
    const float* wmat = (og0 < 96) ? (wh + og0*CC) : (wl + (og0-96)*CC);
    const float* dw   = (og0 < 96) ? (dwh + og0*9) : (dwl + (og0-96)*9);
    float* outbase    = (og0 < 96) ? (g_kvh + ((size_t)b*96 + og0)*HW)
                                   : (g_kvl + ((size_t)b*96 + og0-96)*HW);
    int r0 = rt*8, t = threadIdx.x;
    for (int i = t; i < 12*48; i += 256) sw[i] = wmat[i];
    __syncthreads();
    const float* xb = x + (size_t)b*CC*HW;
    #pragma unroll
    for (int k = 0; k < 5; k++){
        int pt = t + k*256;
        int rr = pt >> 7, w = pt & 127;
        int gr = r0 - 1 + rr;
        float acc[12];
        #pragma unroll
        for (int o2 = 0; o2 < 12; o2++) acc[o2] = 0.f;
        if (gr >= 0 && gr <= 127){
            const float* xp = xb + gr*128 + w;
            #pragma unroll
            for (int c = 0; c < CC; c++){
                float xv = __ldg(xp + (size_t)c*HW);
                #pragma unroll
                for (int o2 = 0; o2 < 12; o2++) acc[o2] += sw[o2*48 + c]*xv;
            }
        }
        #pragma unroll
        for (int o2 = 0; o2 < 12; o2++) cs[(o2*10 + rr)*130 + w + 1] = acc[o2];
    }
    if (t < 120){ int o2 = t/10, rr = t%10; cs[(o2*10+rr)*130] = 0.f; cs[(o2*10+rr)*130 + 129] = 0.f; }
    __syncthreads();
    #pragma unroll
    for (int k = 0; k < 48; k++){
        int task = t + k*256;
        int o2 = task >> 10, p = task & 1023;
        int rr = p >> 7, w = p & 127;
        const float* f = dw + o2*9;
        float acc = 0.f;
        #pragma unroll
        for (int i = 0; i < 3; i++)
            #pragma unroll
            for (int j = 0; j < 3; j++)
                acc += __ldg(&f[i*3+j]) * cs[(o2*10 + rr + i)*130 + w + j];
        outbase[(size_t)o2*HW + (r0+rr)*128 + w] = acc;
    }
}

// ---------------- K9: fused q conv1x1 + dw3 + gram (per b,head,rowtile) ------
__global__ void __launch_bounds__(256,1)
k_qgram(const float* __restrict__ fin, const float* __restrict__ qw,
        const float* __restrict__ qdw, const float* __restrict__ kv,
        float* __restrict__ G){
    extern __shared__ float sh[];
    float* cs = sh;                   // 12*10*130 = 15600
    float* qs = sh + 15600;           // 12*1024
    float* sw = qs + 12*1024;         // 12*48
    int rt = blockIdx.x, hd = blockIdx.y, b = blockIdx.z;
    int r0 = rt*8, t = threadIdx.x;
    for (int i = t; i < 12*48; i += 256) sw[i] = qw[hd*12*CC + i];
    __syncthreads();
    const float* fb = fin + (size_t)b*CC*HW;
    #pragma unroll
    for (int k = 0; k < 5; k++){
        int pt = t + k*256;
        int rr = pt >> 7, w = pt & 127;
        int gr = r0 - 1 + rr;
        float acc[12];
        #pragma unroll
        for (int o2 = 0; o2 < 12; o2++) acc[o2] = 0.f;
        if (gr >= 0 && gr <= 127){
            const float* xp = fb + gr*128 + w;
            #pragma unroll
            for (int c = 0; c < CC; c++){
                float xv = __ldg(xp + (size_t)c*HW);
                #pragma unroll
                for (int o2 = 0; o2 < 12; o2++) acc[o2] += sw[o2*48 + c]*xv;
            }
        }
        #pragma unroll
        for (int o2 = 0; o2 < 12; o2++) cs[(o2*10 + rr)*130 + w + 1] = acc[o2];
    }
    if (t < 120){ int o2 = t/10, rr = t%10; cs[(o2*10+rr)*130] = 0.f; cs[(o2*10+rr)*130 + 129] = 0.f; }
    __syncthreads();
    #pragma unroll
    for (int k = 0; k < 48; k++){
        int task = t + k*256;
        int o2 = task >> 10, p = task & 1023;
        int rr = p >> 7, w = p & 127;
        const float* f = qdw + (hd*12 + o2)*9;
        float acc = 0.f;
        #pragma unroll
        for (int i = 0; i < 3; i++)
            #pragma unroll
            for (int j = 0; j < 3; j++)
                acc += __ldg(&f[i*3+j]) * cs[(o2*10 + rr + i)*130 + w + j];
        qs[o2*1024 + p] = acc;
    }
    __syncthreads();
    float acc[168];
    #pragma unroll
    for (int i = 0; i < 168; i++) acc[i] = 0.f;
    const float* kb = kv + ((size_t)b*96 + hd*12)*HW + (size_t)r0*128;
    for (int p = t; p < 1024; p += 256){
        float qv[12], kvv[12];
        #pragma unroll
        for (int d = 0; d < 12; d++){ qv[d] = qs[d*1024 + p]; kvv[d] = __ldg(&kb[(size_t)d*HW + p]); }
        #pragma unroll
        for (int d = 0; d < 12; d++){
            #pragma unroll
            for (int e = 0; e < 12; e++) acc[d*12+e] += qv[d]*kvv[e];
            acc[144+d] += qv[d]*qv[d];
            acc[156+d] += kvv[d]*kvv[d];
        }
    }
    int lane = t & 31;
    float* Gp = G + (b*NHEADS + hd)*168;
    #pragma unroll
    for (int i = 0; i < 168; i++){
        float v = acc[i];
        #pragma unroll
        for (int off = 16; off; off >>= 1) v += __shfl_down_sync(0xffffffffu, v, off);
        if (lane == 0) atomicAdd(&Gp[i], v);
    }
}

// ---------------- K10: per-batch fused N = fp_slice @ pw @ BD(softmax(S)) ----
__global__ void k_prepN(const float* __restrict__ pw, const float* __restrict__ temp,
                        const float* __restrict__ fpw, int path){
    int b = blockIdx.x, t = threadIdx.x;
    __shared__ float A[4*12*12];
    __shared__ float M[48*48];
    const float* Gb = g_G + ((size_t)path*BB + b)*NHEADS*168;
    if (t < 48){
        int hd = t/12, d = t%12;
        const float* Gh = Gb + hd*168;
        float nq = fmaxf(sqrtf(Gh[144+d]), 1e-12f);
        float tp = temp[hd];
        float row[12]; float mx = -1e30f;
        #pragma unroll
        for (int e = 0; e < 12; e++){
            float nk = fmaxf(sqrtf(Gh[156+e]), 1e-12f);
            row[e] = Gh[d*12+e]/(nq*nk)*tp;
            mx = fmaxf(mx, row[e]);
        }
        float s = 0.f;
        #pragma unroll
        for (int e = 0; e < 12; e++){ row[e] = expf(row[e]-mx); s += row[e]; }
        #pragma unroll
        for (int e = 0; e < 12; e++) A[(hd*12+d)*12 + e] = row[e]/s;
    }
    __syncthreads();
    for (int task = t; task < 2304; task += blockDim.x){
        int o = task/48, cg = task%48; int he = cg/12, e = cg%12;
        float acc = 0.f;
        #pragma unroll
        for (int d = 0; d < 12; d++) acc += pw[o*48 + he*12 + d]*A[(he*12+d)*12 + e];
        M[task] = acc;
    }
    __syncthreads();
    float* Nout = g_N + ((size_t)path*BB + b)*2304;
    for (int task = t; task < 2304; task += blockDim.x){
        int o2 = task/48, cg = task%48;
        float acc = 0.f;
        #pragma unroll
        for (int o = 0; o < 48; o++) acc += fpw[o2*96 + path*48 + o]*M[o*48 + cg];
        Nout[task] = acc;
    }
}

// ---------------- K11: final fused out = Nh@v_h + Nl@v_l + fp_b + x ----------
__global__ void __launch_bounds__(256)
k_final(const float* __restrict__ x, const float* __restrict__ fpb,
        float* __restrict__ out){
    __shared__ float sv[2*CC*64];
    __shared__ float sn[2*2304];
    int b = blockIdx.y; int p0 = blockIdx.x*64; int t = threadIdx.x;
    for (int idx = t; idx < 2304; idx += 256){
        sn[idx]        = g_N[(size_t)b*2304 + idx];
        sn[2304 + idx] = g_N[(size_t)(BB + b)*2304 + idx];
    }
    for (int idx = t; idx < CC*64; idx += 256){
        int c = idx >> 6, p = idx & 63;
        sv[idx]         = g_kvh[(size_t)(b*2*CC + CC + c)*HW + p0 + p];
        sv[CC*64 + idx] = g_kvl[(size_t)(b*2*CC + CC + c)*HW + p0 + p];
    }
    __syncthreads();
    for (int task = t; task < CC*64; task += 256){
        int o = task >> 6, p = task & 63;
        float acc = __ldg(&fpb[o]);
        #pragma unroll
        for (int c = 0; c < CC; c++) acc += sn[o*CC + c]*sv[c*64 + p];
        #pragma unroll
        for (int c = 0; c < CC; c++) acc += sn[2304 + o*CC + c]*sv[CC*64 + c*64 + p];
        size_t gi = (size_t)(b*CC + o)*HW + p0 + p;
        out[gi] = acc + x[gi];
    }
}

// ============================================================================
extern "C" void kernel_launch(void* const* d_in, const int* in_sizes, int n_in,
                              void* d_out, int out_size){
    const float* x       = (const float*)d_in[0];
    const float* fd_w    = (const float*)d_in[1];
    const float* bn_g    = (const float*)d_in[2];
    const float* bn_b    = (const float*)d_in[3];
    const float* bn_m    = (const float*)d_in[4];
    const float* bn_v    = (const float*)d_in[5];
    const float* fh_w1   = (const float*)d_in[6];
    const float* fh_b1   = (const float*)d_in[7];
    const float* fh_w2   = (const float*)d_in[8];
    const float* fh_b2   = (const float*)d_in[9];
    const float* fl_w    = (const float*)d_in[10];
    const float* fl_b    = (const float*)d_in[11];
    const float* hfa_qw  = (const float*)d_in[12];
    const float* hfa_kvw = (const float*)d_in[13];
    const float* hfa_qdw = (const float*)d_in[14];
    const float* hfa_kvdw= (const float*)d_in[15];
    const float* hfa_pw  = (const float*)d_in[16];
    const float* hfa_t   = (const float*)d_in[17];
    const float* lfa_qw  = (const float*)d_in[18];
    const float* lfa_kvw = (const float*)d_in[19];
    const float* lfa_qdw = (const float*)d_in[20];
    const float* lfa_kvdw= (const float*)d_in[21];
    const float* lfa_pw  = (const float*)d_in[22];
    const float* lfa_t   = (const float*)d_in[23];
    const float* fp_w    = (const float*)d_in[24];
    const float* fp_b    = (const float*)d_in[25];

    float *p_hf, *p_lf, *p_kvh, *p_kvl, *p_G;
    cudaGetSymbolAddress((void**)&p_hf,  g_hf);
    cudaGetSymbolAddress((void**)&p_lf,  g_lf);
    cudaGetSymbolAddress((void**)&p_kvh, g_kvh);
    cudaGetSymbolAddress((void**)&p_kvl, g_kvl);
    cudaGetSymbolAddress((void**)&p_G,   g_G);

    // mix weights to constant memory (LDC broadcast in k_fftmix)
    cudaMemcpyToSymbolAsync(c_flw, fl_w, 96*96*sizeof(float), 0,
                            cudaMemcpyDeviceToDevice, 0);
    cudaMemcpyToSymbolAsync(c_flb, fl_b, 96*sizeof(float), 0,
                            cudaMemcpyDeviceToDevice, 0);

    const int SM_CONVDW = (12*10*130 + 12*48)*4;             // 64,704 B
    const int SM_QGRAM  = (12*10*130 + 12*1024 + 12*48)*4;   // 113,856 B
    cudaFuncSetAttribute(k_convdw, cudaFuncAttributeMaxDynamicSharedMemorySize, SM_CONVDW);
    cudaFuncSetAttribute(k_qgram,  cudaFuncAttributeMaxDynamicSharedMemorySize, SM_QGRAM);

    k_mean <<<BB*CC, 256>>>(x);
    k_filt <<<BB, 128>>>(fd_w, bn_g, bn_b, bn_m, bn_v);
    k_split<<<dim3(BB*CC, 8), 256>>>(x, fh_w1, fh_b1, fh_w2, fh_b2);

    // low branch spectral path
    k_rowfft <<<dim3(BB*CC, 4), 256>>>();
    k_fftmix <<<BB*WR, 256>>>();
    k_rowifft<<<dim3(BB*CC, 4), 256>>>();

    // kv for both paths, fused conv+dw
    k_convdw<<<dim3(16, 16, BB), 256, SM_CONVDW>>>(x, hfa_kvw, lfa_kvw, hfa_kvdw, lfa_kvdw);

    // q paths fused conv+dw+gram
    k_qgram<<<dim3(16, NHEADS, BB), 256, SM_QGRAM>>>(p_hf, hfa_qw, hfa_qdw, p_kvh, p_G);
    k_prepN<<<BB, 256>>>(hfa_pw, hfa_t, fp_w, 0);
    k_qgram<<<dim3(16, NHEADS, BB), 256, SM_QGRAM>>>(p_lf, lfa_qw, lfa_qdw, p_kvl, p_G + BB*NHEADS*168);
    k_prepN<<<BB, 256>>>(lfa_pw, lfa_t, fp_w, 1);

    // fused attn@v + pw + concat + fp + bias + residual
    k_final<<<dim3(256, BB), 256>>>(x, fp_b, (float*)d_out);
}